// round 1
// baseline (speedup 1.0000x reference)
#include <cuda_runtime.h>

#define S 26
#define D 7
#define DA 11
#define V 29

__global__ __launch_bounds__(256, 1)
void bes_transformer_kernel(
    const int*   __restrict__ x,
    const float* __restrict__ emb_table,
    const float* __restrict__ pos,
    const float* __restrict__ wk0, const float* __restrict__ bk0,
    const float* __restrict__ wq0, const float* __restrict__ bq0,
    const float* __restrict__ wv0, const float* __restrict__ bv0,
    const float* __restrict__ wf0, const float* __restrict__ bf0,
    const float* __restrict__ wk1, const float* __restrict__ bk1,
    const float* __restrict__ wq1, const float* __restrict__ bq1,
    const float* __restrict__ wv1, const float* __restrict__ bv1,
    const float* __restrict__ wf1, const float* __restrict__ bf1,
    const float* __restrict__ wout, const float* __restrict__ bout,
    float* __restrict__ out)
{
    __shared__ float h[S][D];
    __shared__ float k[S][DA];
    __shared__ float q[S][DA];
    __shared__ float v[S][DA];
    __shared__ float att[S][S];
    __shared__ float res[S][DA];

    const int t  = threadIdx.x;
    const int nt = blockDim.x;

    // ---- embedding + positional ----
    for (int i = t; i < S * D; i += nt) {
        int s = i / D, d = i % D;
        h[s][d] = emb_table[x[s] * D + d] + pos[i];
    }
    __syncthreads();

    #pragma unroll 1
    for (int layer = 0; layer < 2; layer++) {
        const float* wk = layer ? wk1 : wk0;
        const float* bk = layer ? bk1 : bk0;
        const float* wq = layer ? wq1 : wq0;
        const float* bq = layer ? bq1 : bq0;
        const float* wv = layer ? wv1 : wv0;
        const float* bv = layer ? bv1 : bv0;
        const float* wf = layer ? wf1 : wf0;
        const float* bf = layer ? bf1 : bf0;

        // ---- K, Q, V projections: [S, DA] ----
        for (int i = t; i < S * DA; i += nt) {
            int s = i / DA, a = i % DA;
            float sk = bk[a], sq = bq[a], sv = bv[a];
            #pragma unroll
            for (int d = 0; d < D; d++) {
                float hv = h[s][d];
                sk += hv * wk[a * D + d];
                sq += hv * wq[a * D + d];
                sv += hv * wv[a * D + d];
            }
            k[s][a] = sk; q[s][a] = sq; v[s][a] = sv;
        }
        __syncthreads();

        // ---- attention scores (causal only; upper triangle handled in softmax) ----
        for (int i = t; i < S * S; i += nt) {
            int r = i / S, c = i % S;
            if (c <= r) {
                float sum = 0.f;
                #pragma unroll
                for (int a = 0; a < DA; a++) sum += q[r][a] * k[c][a];
                att[r][c] = sum;
            }
        }
        __syncthreads();

        // ---- causal softmax: one thread per row ----
        if (t < S) {
            float m = att[t][0];
            for (int c = 1; c <= t; c++) m = fmaxf(m, att[t][c]);
            float sum = 0.f;
            for (int c = 0; c <= t; c++) {
                float e = expf(att[t][c] - m);
                att[t][c] = e;
                sum += e;
            }
            float inv = 1.f / sum;
            for (int c = 0; c <= t; c++) att[t][c] *= inv;
            for (int c = t + 1; c < S; c++) att[t][c] = 0.f;
        }
        __syncthreads();

        // ---- res = att @ v : [S, DA] ----
        for (int i = t; i < S * DA; i += nt) {
            int s = i / DA, a = i % DA;
            float r = 0.f;
            for (int c = 0; c <= s; c++) r += att[s][c] * v[c][a];
            res[s][a] = r;
        }
        __syncthreads();

        // ---- h = res @ wf^T + bf : [S, D] ----
        for (int i = t; i < S * D; i += nt) {
            int s = i / D, d = i % D;
            float r = bf[d];
            #pragma unroll
            for (int a = 0; a < DA; a++) r += res[s][a] * wf[d * DA + a];
            h[s][d] = r;
        }
        __syncthreads();

        // ---- second-layer attention matrix is part of the output ----
        if (layer == 1) {
            for (int i = t; i < S * S; i += nt)
                out[S * V + i] = att[i / S][i % S];
        }
    }

    // ---- logits: out = h @ wout^T + bout : [S, V] ----
    for (int i = t; i < S * V; i += nt) {
        int s = i / V, vv = i % V;
        float r = bout[vv];
        #pragma unroll
        for (int d = 0; d < D; d++) r += h[s][d] * wout[vv * D + d];
        out[s * V + vv] = r;
    }
}

extern "C" void kernel_launch(void* const* d_in, const int* in_sizes, int n_in,
                              void* d_out, int out_size)
{
    bes_transformer_kernel<<<1, 256>>>(
        (const int*)  d_in[0],   // x
        (const float*)d_in[1],   // emb_table
        (const float*)d_in[2],   // pos
        (const float*)d_in[3],  (const float*)d_in[4],   // w_k0, b_k0
        (const float*)d_in[5],  (const float*)d_in[6],   // w_q0, b_q0
        (const float*)d_in[7],  (const float*)d_in[8],   // w_v0, b_v0
        (const float*)d_in[9],  (const float*)d_in[10],  // w_f0, b_f0
        (const float*)d_in[11], (const float*)d_in[12],  // w_k1, b_k1
        (const float*)d_in[13], (const float*)d_in[14],  // w_q1, b_q1
        (const float*)d_in[15], (const float*)d_in[16],  // w_v1, b_v1
        (const float*)d_in[17], (const float*)d_in[18],  // w_f1, b_f1
        (const float*)d_in[19], (const float*)d_in[20],  // w_out, b_out
        (float*)d_out);
}